// round 12
// baseline (speedup 1.0000x reference)
#include <cuda_runtime.h>
#include <cstdint>

#define GRID_N   7
#define NB       2
#define NC       20
#define IS       8
#define DCH      30
#define L_BOX    5.0f
#define L_NEG    0.5f

#define TPB      256
#define WARPS    (TPB / 32)
#define MAX_BLOCKS 4096

__device__ double g_partials[MAX_BLOCKS];
__device__ unsigned int g_count = 0;

__device__ __forceinline__ void cp_async8(uint32_t dst, const void* src) {
    asm volatile("cp.async.ca.shared.global [%0], [%1], 8;\n" :: "r"(dst), "l"(src));
}
__device__ __forceinline__ void cp_commit() {
    asm volatile("cp.async.commit_group;\n" ::: "memory");
}
__device__ __forceinline__ void cp_wait0() {
    asm volatile("cp.async.wait_group 0;\n" ::: "memory");
}

__device__ __forceinline__ float bce_t(float x) {           // 1 + exp(-|x|)
    return 1.0f + __expf(-fabsf(x));
}

__device__ __forceinline__ float box_loss_f(const float* pb, const float* gb) {
    float dx = pb[0] - gb[0];
    float dy = pb[1] - gb[1];
    float sw = sqrtf(fabsf(pb[2])) - sqrtf(gb[2]);
    float sh = sqrtf(fabsf(pb[3])) - sqrtf(gb[3]);
    return dx * dx + dy * dy + sw * sw + sh * sh;
}

// box + conf part given registers. cls handled elsewhere.
__device__ __forceinline__ float boxconf_loss(const float pv[IS], const float gv[IS],
                                              float pc8, float pc9,
                                              float conf_g, int cellIdx) {
    if (conf_g > 0.0f) {
        int cell = cellIdx % (GRID_N * GRID_N);
        float col = (float)(cell % GRID_N);
        float row = (float)(cell / GRID_N);

        float poff[NB][4], gbox[NB][4];
        #pragma unroll
        for (int b = 0; b < NB; b++) {
            poff[b][0] = __fdividef(1.0f, 1.0f + __expf(-pv[4 * b + 0]));
            poff[b][1] = __fdividef(1.0f, 1.0f + __expf(-pv[4 * b + 1]));
            poff[b][2] = pv[4 * b + 2];
            poff[b][3] = pv[4 * b + 3];
            gbox[b][0] = gv[4 * b + 0];
            gbox[b][1] = gv[4 * b + 1];
            gbox[b][2] = gv[4 * b + 2];
            gbox[b][3] = gv[4 * b + 3];
        }

        float pl[NB][4], gl[NB][4];
        #pragma unroll
        for (int b = 0; b < NB; b++) {
            float cx = (poff[b][0] + col) * (1.0f / GRID_N);
            float cy = (poff[b][1] + row) * (1.0f / GRID_N);
            float w  = poff[b][2], h = poff[b][3];
            pl[b][0] = cx - w * 0.5f; pl[b][1] = cy - h * 0.5f;
            pl[b][2] = cx + w * 0.5f; pl[b][3] = cy + h * 0.5f;
            float gx = (gbox[b][0] + col) * (1.0f / GRID_N);
            float gy = (gbox[b][1] + row) * (1.0f / GRID_N);
            float gw = gbox[b][2], gh = gbox[b][3];
            gl[b][0] = gx - gw * 0.5f; gl[b][1] = gy - gh * 0.5f;
            gl[b][2] = gx + gw * 0.5f; gl[b][3] = gy + gh * 0.5f;
        }

        float iou[NB][NB];
        #pragma unroll
        for (int pi = 0; pi < NB; pi++) {
            #pragma unroll
            for (int gi = 0; gi < NB; gi++) {
                float ltx = fmaxf(pl[pi][0], gl[gi][0]);
                float lty = fmaxf(pl[pi][1], gl[gi][1]);
                float rbx = fminf(pl[pi][2], gl[gi][2]);
                float rby = fminf(pl[pi][3], gl[gi][3]);
                float wx = fmaxf(rbx - ltx, 0.0f);
                float wy = fmaxf(rby - lty, 0.0f);
                float inter = wx * wy;
                float aa = (pl[pi][2] - pl[pi][0]) * (pl[pi][3] - pl[pi][1]);
                float ab = (gl[gi][2] - gl[gi][0]) * (gl[gi][3] - gl[gi][1]);
                iou[pi][gi] = __fdividef(inter, aa + ab - inter + 1e-7f);
            }
        }

        int ind0 = (iou[1][0] > iou[0][0]) ? 1 : 0;
        int ind1 = (iou[1][1] > iou[0][1]) ? 1 : 0;

        bool same_g = (gbox[0][0] == gbox[1][0]) && (gbox[0][1] == gbox[1][1]) &&
                      (gbox[0][2] == gbox[1][2]) && (gbox[0][3] == gbox[1][3]);
        bool same_ind = (ind0 == ind1);

        float box_cell;
        if (same_g) {
            box_cell = box_loss_f(poff[ind0], gbox[0]);
        } else if (same_ind) {
            box_cell = box_loss_f(poff[0], gbox[0]) + box_loss_f(poff[1], gbox[1]);
        } else {
            box_cell = box_loss_f(poff[ind0], gbox[0]) + box_loss_f(poff[ind1], gbox[1]);
        }

        float conf_cell;
        if (same_g) {
            float x = ind1 ? pc9 : pc8;
            conf_cell = fmaxf(x, 0.f) - x + __logf(bce_t(x));
        } else {
            conf_cell = fmaxf(pc8, 0.f) - pc8 + fmaxf(pc9, 0.f) - pc9
                      + __logf(bce_t(pc8) * bce_t(pc9));
        }
        return L_BOX * box_cell + conf_cell;
    } else {
        return L_NEG * (fmaxf(pc8, 0.f) + fmaxf(pc9, 0.f)
                        + __logf(bce_t(pc8) * bce_t(pc9)));
    }
}

// full per-lane path (tail only): everything direct from gmem, incl. cls.
__device__ __forceinline__ float cell_loss_direct(const float* __restrict__ pc,
                                                  const float* __restrict__ gc,
                                                  int cellIdx) {
    const float2* pc2 = reinterpret_cast<const float2*>(pc);
    const float2* gc2 = reinterpret_cast<const float2*>(gc);
    float2 pcf = pc2[4];
    float conf_g = gc2[4].x;

    float pv[IS], gv[IS];
    #pragma unroll
    for (int i = 0; i < 4; i++) {
        float2 a = pc2[i]; pv[2*i] = a.x; pv[2*i+1] = a.y;
        float2 b = gc2[i]; gv[2*i] = b.x; gv[2*i+1] = b.y;
    }

    float acc = boxconf_loss(pv, gv, pcf.x, pcf.y, conf_g, cellIdx);

    if (conf_g > 0.0f) {
        const float2* pcl2 = reinterpret_cast<const float2*>(pc + NB * 5);
        const float2* gcl2 = reinterpret_cast<const float2*>(gc + NB * 5);
        float lin = 0.0f, prod = 1.0f;
        #pragma unroll
        for (int i = 0; i < NC / 2; i++) {
            float2 a = pcl2[i];
            float2 b = gcl2[i];
            lin  += fmaxf(a.x, 0.f) - a.x * b.x + fmaxf(a.y, 0.f) - a.y * b.y;
            prod *= bce_t(a.x) * bce_t(a.y);
        }
        acc += lin + __logf(prod);
    }
    return acc;
}

__global__ void __launch_bounds__(TPB)
yolo_loss_kernel(const float* __restrict__ p, const float* __restrict__ g,
                 int ncells, float* __restrict__ out, float inv_nb) {
    // staged box/conf prefix (floats 0..9) of both tensors: 32 cells x 10 floats
    __shared__ float sP10[WARPS][320];   // 8 * 1280 B
    __shared__ float sG10[WARPS][320];   // 8 * 1280 B   (total 20.5 KB)

    const int tid  = threadIdx.x;
    const int lane = tid & 31;
    const int wid  = tid >> 5;
    const int t    = blockIdx.x * WARPS + wid;   // this warp's 32-cell tile
    const int c0   = t * 32;

    float acc = 0.0f;

    if (c0 + 32 <= ncells) {
        // ========== 1) stage p/g box+conf prefix via cp.async.ca 8B ==========
        {
            const char* pbase = reinterpret_cast<const char*>(p + (size_t)c0 * DCH);
            const char* gbase = reinterpret_cast<const char*>(g + (size_t)c0 * DCH);
            uint32_t pd = (uint32_t)__cvta_generic_to_shared(&sP10[wid][0]);
            uint32_t gd = (uint32_t)__cvta_generic_to_shared(&sG10[wid][0]);
            #pragma unroll
            for (int k = 0; k < 5; k++) {
                int j = lane + 32 * k;        // 0..159
                int cell = j / 5;             // mul-shift
                int ch   = j - 5 * cell;      // 0..4 (8B chunk)
                int soff = cell * 40 + ch * 8;
                cp_async8(pd + soff, pbase + cell * 120 + ch * 8);
                cp_async8(gd + soff, gbase + cell * 120 + ch * 8);
            }
            cp_commit();
        }

        // ========== 2) cls loads, channel-parallel, shared index math ==========
        // tile's cls region: 32 cells x 10 float2 pairs; lane handles q=j*32+lane
        const float2* pt2 = reinterpret_cast<const float2*>(p) + (size_t)t * 480;
        const float2* gt2 = reinterpret_cast<const float2*>(g) + (size_t)t * 480;
        float2 pa[10], ga[10];
        int    cq[10];
        #pragma unroll
        for (int j = 0; j < 10; j++) {
            int q = j * 32 + lane;
            int cell = q / 10;                // 0..31
            int pair = q - 10 * cell;         // 0..9
            int off  = cell * 15 + 5 + pair;  // float2 index within tile
            cq[j] = cell;
            pa[j] = __ldg(pt2 + off);
            ga[j] = __ldg(gt2 + off);
        }

        // ========== 3) wait for staged prefix, build positive mask ==========
        cp_wait0();
        __syncwarp();
        float conf_g = sG10[wid][lane * 10 + IS];
        unsigned mb = __ballot_sync(0xffffffffu, conf_g > 0.0f);

        // ========== 4) cls masked accumulation ==========
        {
            float lin = 0.0f, prod = 1.0f;
            #pragma unroll
            for (int j = 0; j < 10; j++) {
                float2 a = pa[j];
                float2 b = ga[j];
                bool m = (mb >> cq[j]) & 1u;
                float lq = fmaxf(a.x, 0.f) - a.x * b.x + fmaxf(a.y, 0.f) - a.y * b.y;
                float pq = bce_t(a.x) * bce_t(a.y);
                lin  += m ? lq : 0.0f;
                prod *= m ? pq : 1.0f;
            }
            acc += lin + __logf(prod);   // prod <= 2^20: safe
        }

        // ========== 5) per-lane box/conf from smem ==========
        {
            const float* ps = &sP10[wid][lane * 10];
            const float* gs = &sG10[wid][lane * 10];
            float pv[IS], gv[IS];
            #pragma unroll
            for (int i = 0; i < IS; i++) { pv[i] = ps[i]; gv[i] = gs[i]; }
            acc += boxconf_loss(pv, gv, ps[8], ps[9], conf_g, c0 + lane);
        }
    } else if (c0 + lane < ncells) {
        // ========== tail: per-lane direct ==========
        int idx = c0 + lane;
        acc = cell_loss_direct(p + (size_t)idx * DCH, g + (size_t)idx * DCH, idx);
    }

    // ---- deterministic block reduction ----
    #pragma unroll
    for (int o = 16; o > 0; o >>= 1)
        acc += __shfl_down_sync(0xffffffffu, acc, o);

    __shared__ float warp_sums[WARPS];
    if (lane == 0) warp_sums[wid] = acc;
    __syncthreads();

    if (tid == 0) {
        float v = 0.0f;
        #pragma unroll
        for (int w = 0; w < WARPS; w++) v += warp_sums[w];
        g_partials[blockIdx.x] = (double)v;
    }

    // ---- last-block finalization (deterministic fixed-order sum) ----
    __shared__ bool isLast;
    if (tid == 0) {
        __threadfence();
        unsigned int v = atomicAdd(&g_count, 1u);
        isLast = (v == gridDim.x - 1);
    }
    __syncthreads();

    if (isLast) {
        __shared__ double sh[TPB];
        double s = 0.0;
        for (int i = tid; i < (int)gridDim.x; i += TPB)
            s += g_partials[i];
        sh[tid] = s;
        __syncthreads();
        #pragma unroll
        for (int strideR = TPB / 2; strideR > 0; strideR >>= 1) {
            if (tid < strideR) sh[tid] += sh[tid + strideR];
            __syncthreads();
        }
        if (tid == 0) {
            out[0] = (float)(sh[0] * (double)inv_nb);
            g_count = 0;   // reset for next graph replay
        }
    }
}

extern "C" void kernel_launch(void* const* d_in, const int* in_sizes, int n_in,
                              void* d_out, int out_size) {
    const float* p = (const float*)d_in[0];
    const float* g = (const float*)d_in[1];
    float* out = (float*)d_out;

    int ncells = in_sizes[0] / DCH;                 // B * 49
    int batch  = ncells / (GRID_N * GRID_N);        // B
    int warptiles = (ncells + 31) / 32;
    int nblocks = (warptiles + WARPS - 1) / WARPS;
    if (nblocks > MAX_BLOCKS) nblocks = MAX_BLOCKS; // never hit for this size

    yolo_loss_kernel<<<nblocks, TPB>>>(p, g, ncells, out, 1.0f / (float)batch);
}

// round 13
// speedup vs baseline: 1.0014x; 1.0014x over previous
#include <cuda_runtime.h>
#include <cstdint>

#define GRID_N   7
#define NB       2
#define NC       20
#define IS       8
#define DCH      30
#define L_BOX    5.0f
#define L_NEG    0.5f

#define TPB      128
#define WARPS    (TPB / 32)
#define NBLOCKS  740            // 148 SMs x 5 blocks (41KB smem each) = one wave
#define MAX_BLOCKS 2048

#define P4       240            // p tile: 32 cells x 30 floats = 240 float4
#define G4       80             // g prefix: 32 cells x 10 floats = 80 float4
#define ST4      (P4 + G4)      // 320 float4 = 5120 B per stage

__device__ double g_partials[MAX_BLOCKS];
__device__ unsigned int g_count = 0;

__device__ __forceinline__ void cp_async16(uint32_t dst, const void* src) {
    asm volatile("cp.async.cg.shared.global [%0], [%1], 16;\n" :: "r"(dst), "l"(src));
}
__device__ __forceinline__ void cp_async8(uint32_t dst, const void* src) {
    asm volatile("cp.async.ca.shared.global [%0], [%1], 8;\n" :: "r"(dst), "l"(src));
}
__device__ __forceinline__ void cp_commit() {
    asm volatile("cp.async.commit_group;\n" ::: "memory");
}
__device__ __forceinline__ void cp_wait1() {
    asm volatile("cp.async.wait_group 1;\n" ::: "memory");
}
__device__ __forceinline__ void cp_wait0() {
    asm volatile("cp.async.wait_group 0;\n" ::: "memory");
}

__device__ __forceinline__ float bce_t(float x) {           // 1 + exp(-|x|)
    return 1.0f + __expf(-fabsf(x));
}

__device__ __forceinline__ float box_loss_f(const float* pb, const float* gb) {
    float dx = pb[0] - gb[0];
    float dy = pb[1] - gb[1];
    float sw = sqrtf(fabsf(pb[2])) - sqrtf(gb[2]);
    float sh = sqrtf(fabsf(pb[3])) - sqrtf(gb[3]);
    return dx * dx + dy * dy + sw * sw + sh * sh;
}

// positive-cell box+conf; NOTE: col/row dropped — IoU is invariant to the
// common +cr/GRID shift, and box_loss/conf never use it.
// returns L_BOX*box_cell + conf linear part; multiplies *conf_prod by the
// conf bce_t product (its log gets merged with the cls log by the caller).
__device__ __forceinline__ float boxconf_pos(const float pv[IS], const float gv[IS],
                                             float pc8, float pc9, float* conf_prod) {
    float poff[NB][4], gbox[NB][4];
    #pragma unroll
    for (int b = 0; b < NB; b++) {
        poff[b][0] = __fdividef(1.0f, 1.0f + __expf(-pv[4 * b + 0]));
        poff[b][1] = __fdividef(1.0f, 1.0f + __expf(-pv[4 * b + 1]));
        poff[b][2] = pv[4 * b + 2];
        poff[b][3] = pv[4 * b + 3];
        gbox[b][0] = gv[4 * b + 0];
        gbox[b][1] = gv[4 * b + 1];
        gbox[b][2] = gv[4 * b + 2];
        gbox[b][3] = gv[4 * b + 3];
    }

    // ltrb without the common cell shift
    float pl[NB][4], gl[NB][4];
    #pragma unroll
    for (int b = 0; b < NB; b++) {
        float cx = poff[b][0] * (1.0f / GRID_N);
        float cy = poff[b][1] * (1.0f / GRID_N);
        float w  = poff[b][2], h = poff[b][3];
        pl[b][0] = cx - w * 0.5f; pl[b][1] = cy - h * 0.5f;
        pl[b][2] = cx + w * 0.5f; pl[b][3] = cy + h * 0.5f;
        float gx = gbox[b][0] * (1.0f / GRID_N);
        float gy = gbox[b][1] * (1.0f / GRID_N);
        float gw = gbox[b][2], gh = gbox[b][3];
        gl[b][0] = gx - gw * 0.5f; gl[b][1] = gy - gh * 0.5f;
        gl[b][2] = gx + gw * 0.5f; gl[b][3] = gy + gh * 0.5f;
    }

    float iou[NB][NB];
    #pragma unroll
    for (int pi = 0; pi < NB; pi++) {
        #pragma unroll
        for (int gi = 0; gi < NB; gi++) {
            float ltx = fmaxf(pl[pi][0], gl[gi][0]);
            float lty = fmaxf(pl[pi][1], gl[gi][1]);
            float rbx = fminf(pl[pi][2], gl[gi][2]);
            float rby = fminf(pl[pi][3], gl[gi][3]);
            float wx = fmaxf(rbx - ltx, 0.0f);
            float wy = fmaxf(rby - lty, 0.0f);
            float inter = wx * wy;
            float aa = (pl[pi][2] - pl[pi][0]) * (pl[pi][3] - pl[pi][1]);
            float ab = (gl[gi][2] - gl[gi][0]) * (gl[gi][3] - gl[gi][1]);
            iou[pi][gi] = __fdividef(inter, aa + ab - inter + 1e-7f);
        }
    }

    int ind0 = (iou[1][0] > iou[0][0]) ? 1 : 0;
    int ind1 = (iou[1][1] > iou[0][1]) ? 1 : 0;

    bool same_g = (gbox[0][0] == gbox[1][0]) && (gbox[0][1] == gbox[1][1]) &&
                  (gbox[0][2] == gbox[1][2]) && (gbox[0][3] == gbox[1][3]);
    bool same_ind = (ind0 == ind1);

    float box_cell;
    if (same_g) {
        box_cell = box_loss_f(poff[ind0], gbox[0]);
    } else if (same_ind) {
        box_cell = box_loss_f(poff[0], gbox[0]) + box_loss_f(poff[1], gbox[1]);
    } else {
        box_cell = box_loss_f(poff[ind0], gbox[0]) + box_loss_f(poff[ind1], gbox[1]);
    }

    float conf_lin;
    if (same_g) {
        float x = ind1 ? pc9 : pc8;
        conf_lin = fmaxf(x, 0.f) - x;
        *conf_prod = bce_t(x);
    } else {
        conf_lin = fmaxf(pc8, 0.f) - pc8 + fmaxf(pc9, 0.f) - pc9;
        *conf_prod = bce_t(pc8) * bce_t(pc9);
    }
    return L_BOX * box_cell + conf_lin;
}

// tail-only direct path (everything from gmem)
__device__ __forceinline__ float cell_loss_direct(const float* __restrict__ pc,
                                                  const float* __restrict__ gc) {
    const float2* pc2 = reinterpret_cast<const float2*>(pc);
    const float2* gc2 = reinterpret_cast<const float2*>(gc);
    float2 pcf = pc2[4];
    float conf_g = gc2[4].x;

    float pv[IS], gv[IS];
    #pragma unroll
    for (int i = 0; i < 4; i++) {
        float2 a = pc2[i]; pv[2*i] = a.x; pv[2*i+1] = a.y;
        float2 b = gc2[i]; gv[2*i] = b.x; gv[2*i+1] = b.y;
    }

    if (conf_g > 0.0f) {
        float conf_prod;
        float acc = boxconf_pos(pv, gv, pcf.x, pcf.y, &conf_prod);
        const float2* pcl2 = reinterpret_cast<const float2*>(pc + NB * 5);
        const float2* gcl2 = reinterpret_cast<const float2*>(gc + NB * 5);
        float lin = 0.0f, prod = conf_prod;
        #pragma unroll
        for (int i = 0; i < NC / 2; i++) {
            float2 a = pcl2[i];
            float2 b = gcl2[i];
            lin  += fmaxf(a.x, 0.f) - a.x * b.x + fmaxf(a.y, 0.f) - a.y * b.y;
            prod *= bce_t(a.x) * bce_t(a.y);
        }
        return acc + lin + __logf(prod);
    } else {
        return L_NEG * (fmaxf(pcf.x, 0.f) + fmaxf(pcf.y, 0.f)
                        + __logf(bce_t(pcf.x) * bce_t(pcf.y)));
    }
}

// stage one tile: p full (240 float4, 16B chunks) + g 10-float prefix (8B chunks)
__device__ __forceinline__ void stage_tile(uint32_t dst, const float* __restrict__ p,
                                           const float* __restrict__ g,
                                           int tile, int lane) {
    const float4* psrc = reinterpret_cast<const float4*>(p + (size_t)tile * 32 * DCH) + lane;
    uint32_t pd = dst + lane * 16;
    #pragma unroll
    for (int k = 0; k < 7; k++)
        cp_async16(pd + k * 512, psrc + 32 * k);
    if (lane < 16)
        cp_async16(pd + 7 * 512, psrc + 224);

    const char* gbase = reinterpret_cast<const char*>(g + (size_t)tile * 32 * DCH);
    uint32_t gd = dst + P4 * 16;
    #pragma unroll
    for (int k = 0; k < 5; k++) {
        int j = lane + 32 * k;        // 0..159
        int cell = j / 5;
        int ch   = j - 5 * cell;      // 0..4
        cp_async8(gd + cell * 40 + ch * 8, gbase + cell * 120 + ch * 8);
    }
    cp_commit();
}

__global__ void __launch_bounds__(TPB)
yolo_loss_kernel(const float* __restrict__ p, const float* __restrict__ g,
                 int ncells, float* __restrict__ out, float inv_nb) {
    // per-warp double buffer: [stage][p(240f4) | g10(80f4)]
    __shared__ float4 sbuf[WARPS][2][ST4];    // 4 * 2 * 320 * 16 = 40960 B

    const int tid  = threadIdx.x;
    const int lane = tid & 31;
    const int wid  = tid >> 5;
    const int warpGlobal = blockIdx.x * WARPS + wid;
    const int nwarps = gridDim.x * WARPS;
    const int ntiles = ncells >> 5;

    uint32_t bufA = (uint32_t)__cvta_generic_to_shared(&sbuf[wid][0][0]);
    uint32_t bufB = (uint32_t)__cvta_generic_to_shared(&sbuf[wid][1][0]);

    float acc = 0.0f;

    int t = warpGlobal;
    if (t < ntiles) stage_tile(bufA, p, g, t, lane);

    int cur = 0;
    for (; t < ntiles; t += nwarps) {
        int tn = t + nwarps;
        bool pf = (tn < ntiles);
        if (pf) stage_tile(cur ? bufA : bufB, p, g, tn, lane);

        // g-cls loads for tile t: per-lane direct, issued before the wait so
        // they overlap the staging in flight
        const float2* gcl = reinterpret_cast<const float2*>(
            g + (size_t)t * 32 * DCH + (size_t)lane * DCH + NB * 5);
        float2 gc[10];
        #pragma unroll
        for (int j = 0; j < 10; j++)
            gc[j] = __ldg(gcl + j);

        if (pf) cp_wait1(); else cp_wait0();
        __syncwarp();

        const float* base = reinterpret_cast<const float*>(&sbuf[wid][cur][0]);
        const float* pcell = base + lane * DCH;              // 30 floats
        const float* g10   = base + 4 * P4 + lane * 10;      // 10 floats

        float conf_g = g10[IS];
        const float2* pcf2 = reinterpret_cast<const float2*>(pcell);
        float2 pconf = pcf2[4];

        if (conf_g > 0.0f) {
            float pv[IS], gv[IS];
            #pragma unroll
            for (int i = 0; i < 4; i++) {
                float2 a = pcf2[i]; pv[2*i] = a.x; pv[2*i+1] = a.y;
            }
            #pragma unroll
            for (int i = 0; i < IS; i++) gv[i] = g10[i];

            float conf_prod;
            float part = boxconf_pos(pv, gv, pconf.x, pconf.y, &conf_prod);

            // cls: p from smem, g from regs; single merged log
            const float2* pcl2 = reinterpret_cast<const float2*>(pcell + NB * 5);
            float lin = 0.0f, prod = conf_prod;
            #pragma unroll
            for (int i = 0; i < NC / 2; i++) {
                float2 a = pcl2[i];
                float2 b = gc[i];
                lin  += fmaxf(a.x, 0.f) - a.x * b.x + fmaxf(a.y, 0.f) - a.y * b.y;
                prod *= bce_t(a.x) * bce_t(a.y);
            }
            acc += part + lin + __logf(prod);
        } else {
            acc += L_NEG * (fmaxf(pconf.x, 0.f) + fmaxf(pconf.y, 0.f)
                            + __logf(bce_t(pconf.x) * bce_t(pconf.y)));
        }

        __syncwarp();
        cur ^= 1;
    }

    // tail cells (ncells % 32): block 0, warp 0, direct loads
    if (blockIdx.x == 0 && wid == 0) {
        int idx = ntiles * 32 + lane;
        if (idx < ncells)
            acc += cell_loss_direct(p + (size_t)idx * DCH, g + (size_t)idx * DCH);
    }

    // ---- deterministic block reduction ----
    #pragma unroll
    for (int o = 16; o > 0; o >>= 1)
        acc += __shfl_down_sync(0xffffffffu, acc, o);

    __shared__ float warp_sums[WARPS];
    if (lane == 0) warp_sums[wid] = acc;
    __syncthreads();

    if (tid == 0) {
        float v = 0.0f;
        #pragma unroll
        for (int w = 0; w < WARPS; w++) v += warp_sums[w];
        g_partials[blockIdx.x] = (double)v;
    }

    // ---- last-block finalization (deterministic fixed-order sum) ----
    __shared__ bool isLast;
    if (tid == 0) {
        __threadfence();
        unsigned int v = atomicAdd(&g_count, 1u);
        isLast = (v == gridDim.x - 1);
    }
    __syncthreads();

    if (isLast) {
        __shared__ double sh[TPB];
        double s = 0.0;
        for (int i = tid; i < (int)gridDim.x; i += TPB)
            s += g_partials[i];
        sh[tid] = s;
        __syncthreads();
        #pragma unroll
        for (int strideR = TPB / 2; strideR > 0; strideR >>= 1) {
            if (tid < strideR) sh[tid] += sh[tid + strideR];
            __syncthreads();
        }
        if (tid == 0) {
            out[0] = (float)(sh[0] * (double)inv_nb);
            g_count = 0;   // reset for next graph replay
        }
    }
}

extern "C" void kernel_launch(void* const* d_in, const int* in_sizes, int n_in,
                              void* d_out, int out_size) {
    const float* p = (const float*)d_in[0];
    const float* g = (const float*)d_in[1];
    float* out = (float*)d_out;

    int ncells = in_sizes[0] / DCH;                 // B * 49
    int batch  = ncells / (GRID_N * GRID_N);        // B
    int ntiles = ncells >> 5;

    int nblocks = NBLOCKS;
    int needed = (ntiles + WARPS - 1) / WARPS;
    if (needed < 1) needed = 1;
    if (nblocks > needed) nblocks = needed;
    if (nblocks > MAX_BLOCKS) nblocks = MAX_BLOCKS;

    yolo_loss_kernel<<<nblocks, TPB>>>(p, g, ncells, out, 1.0f / (float)batch);
}